// round 14
// baseline (speedup 1.0000x reference)
#include <cuda_runtime.h>

// SCSA fused v12 = v8 VERBATIM control structure + bodies (152x1024 persistent
// occ-1, loop-top steal between two barriers, position-blocked convs, .cs,
// unroll-8) with two orthogonal changes:
//  1. self-resetting counters (last CTA zeroes g_counter/g_done) -> the
//     reset_counter launch is gone; graph is a single node.
//  2. weight-balanced 1:4 unit interleave: super-block of 5 ids =
//     {spatial(bb), 4x quarter(bb)} -> 50% of DRAM demand comes from
//     pure-streaming channel work at ALL times (v8 hoarded 768 quarters in a
//     tail phase), covering spatial MLP dead time; tail stays quarter-grained.

#define NCTAS   152
#define THREADS 1024
#define NUNITS  1280

__device__ unsigned int g_counter = 0u;
__device__ unsigned int g_done    = 0u;

__device__ __forceinline__ float sigmoidf_(float z) {
    return 1.f / (1.f + __expf(-z));
}
__device__ __forceinline__ float sigapx_(float z) {
    float t;
    asm("tanh.approx.f32 %0, %1;" : "=f"(t) : "f"(z * 0.5f));
    return fmaf(0.5f, t, 0.5f);
}
__device__ __forceinline__ float hswishf_(float z) {
    return z * __saturatef((z + 3.f) * (1.f / 6.f));
}
__device__ __forceinline__ int shuffle_out_ch(int p) {
    return (p < 256) ? (2 * p) : (2 * (p - 256) + 1);
}

__global__ __launch_bounds__(THREADS, 1) void scsa_persistent(
    const float* __restrict__ x,
    const float* __restrict__ cweight, const float* __restrict__ cbias,
    const float* __restrict__ conv1_w, const float* __restrict__ conv1_b,
    const float* __restrict__ gn_g,    const float* __restrict__ gn_b,
    const float* __restrict__ convh_w, const float* __restrict__ convh_b,
    const float* __restrict__ convw_w, const float* __restrict__ convw_b,
    float* __restrict__ out)
{
    __shared__ float s_red[4096];   // row c: xh[0..63] | xw[64..127]; aliased a_h|a_w
    __shared__ float s_y[4096];
    __shared__ float s_w1[1024], s_wh[1024], s_ww[1024];
    __shared__ float s_b1[32], s_bh[32], s_bw[32], s_gg[32], s_gb[32], s_xs[32];
    __shared__ float s_part[32];    // channel-quarter partials [ch8*4 + rowblk]
    __shared__ float s_gate[8];
    __shared__ unsigned s_u;
    float* s_a = s_red;

    const int tid  = threadIdx.x;
    const int wid  = tid >> 5;       // warp id; spatial: warp = channel c
    const int lane = tid & 31;
    const int half = lane >> 4;
    const int q    = lane & 15;
    const int t7   = tid >> 7;       // 0..7 conv output-block id
    const int pp   = tid & 127;      // conv position id
    const int c    = wid;

    // stage weights once
    s_w1[tid] = conv1_w[tid];
    s_wh[tid] = convh_w[tid];
    s_ww[tid] = convw_w[tid];
    if (tid < 32) {
        s_b1[tid] = conv1_b[tid]; s_bh[tid] = convh_b[tid]; s_bw[tid] = convw_b[tid];
        s_gg[tid] = gn_g[tid];    s_gb[tid] = gn_b[tid];
    }

    while (true) {
        __syncthreads();                 // smem quiesce + weight publish
        if (tid == 0) s_u = atomicAdd(&g_counter, 1u);
        __syncthreads();
        const unsigned u = s_u;
        if (u >= NUNITS) break;

        // ---------------- unit decode: super-block of 5 ----------------
        const int bb = (int)(u / 5u);
        const int r  = (int)(u % 5u);
        const bool is_spatial = (r == 0);
        const int qd = r - 1;            // quarter id when !is_spatial
        const int n = bb >> 3, g = bb & 7;

        if (!is_spatial) {
            // ========== channel-quarter: x0 channels g*64 + qd*8 + [0,8) ==========
            const int ch8 = wid & 7;
            const int rb  = wid >> 3;
            const int cglob = g * 64 + qd * 8 + ch8;
            const float4* xq4 = (const float4*)(x + ((size_t)(n * 512 + cglob)) * 4096)
                              + rb * 256;
            float s = 0.f;
            {
                float4 v[8];
                #pragma unroll
                for (int j = 0; j < 8; j++) v[j] = xq4[j * 32 + lane];
                #pragma unroll
                for (int j = 0; j < 8; j++)
                    s += (v[j].x + v[j].y) + (v[j].z + v[j].w);
            }
            #pragma unroll
            for (int o = 16; o; o >>= 1) s += __shfl_xor_sync(0xffffffffu, s, o);
            if (lane == 0) s_part[ch8 * 4 + rb] = s;
            __syncthreads();                  // B1: publishes s_part
            if (tid < 8) {
                const float tot = s_part[tid * 4] + s_part[tid * 4 + 1]
                                + s_part[tid * 4 + 2] + s_part[tid * 4 + 3];
                const int cg = qd * 8 + tid;
                s_gate[tid] = sigmoidf_(cweight[cg] * (tot * (1.f / 4096.f)) + cbias[cg]);
            }
            __syncthreads();                  // B2: publishes s_gate
            const float gate = s_gate[ch8];
            float4* od = (float4*)(out + ((size_t)(n * 512 + shuffle_out_ch(cglob))) * 4096)
                       + rb * 256;
            {
                float4 v[8];
                #pragma unroll
                for (int j = 0; j < 8; j++) v[j] = __ldcs(&xq4[j * 32 + lane]);
                #pragma unroll
                for (int j = 0; j < 8; j++) {
                    v[j].x *= gate; v[j].y *= gate; v[j].z *= gate; v[j].w *= gate;
                    __stcs(&od[j * 32 + lane], v[j]);
                }
            }
            continue;
        }

        // ================= spatial unit: x1 of block bb =================
        const float4* xc4 = (const float4*)(x + ((size_t)(n * 512 + g * 64 + 32 + c)) * 4096);

        // ---- Pass A: row/col/total means. 8 loads in flight per warp. ----
        float cs0 = 0.f, cs1 = 0.f, cs2 = 0.f, cs3 = 0.f, xs = 0.f;
        #pragma unroll
        for (int tt = 0; tt < 32; tt += 8) {
            float4 v[8];
            #pragma unroll
            for (int j = 0; j < 8; j++) v[j] = xc4[(tt + j) * 32 + lane];
            float r8[8];
            #pragma unroll
            for (int j = 0; j < 8; j++) {
                cs0 += v[j].x; cs1 += v[j].y; cs2 += v[j].z; cs3 += v[j].w;
                r8[j] = (v[j].x + v[j].y) + (v[j].z + v[j].w);
                xs += r8[j];
            }
            #pragma unroll
            for (int o = 8; o; o >>= 1) {
                #pragma unroll
                for (int j = 0; j < 8; j++)
                    r8[j] += __shfl_xor_sync(0xffffffffu, r8[j], o);
            }
            if (q == 0) {
                #pragma unroll
                for (int j = 0; j < 8; j++)
                    s_red[c * 128 + 2 * (tt + j) + half] = r8[j] * (1.f / 64.f);
            }
        }
        cs0 += __shfl_xor_sync(0xffffffffu, cs0, 16);
        cs1 += __shfl_xor_sync(0xffffffffu, cs1, 16);
        cs2 += __shfl_xor_sync(0xffffffffu, cs2, 16);
        cs3 += __shfl_xor_sync(0xffffffffu, cs3, 16);
        #pragma unroll
        for (int o = 16; o; o >>= 1) xs += __shfl_xor_sync(0xffffffffu, xs, o);
        if (half == 0) {
            ((float4*)(s_red + c * 128 + 64))[q] = make_float4(
                cs0 * (1.f / 64.f), cs1 * (1.f / 64.f),
                cs2 * (1.f / 64.f), cs3 * (1.f / 64.f));
        }
        if (lane == 0) s_xs[c] = xs * (1.f / 4096.f);
        __syncthreads();                      // B1: publishes s_red, s_xs

        // ---- conv1, register-blocked: outputs o = t7, 8+t7, 16+t7, 24+t7 ----
        {
            float acc0 = s_b1[t7], acc1 = s_b1[8 + t7], acc2 = s_b1[16 + t7], acc3 = s_b1[24 + t7];
            const int wb = t7 * 32;
            #pragma unroll 8
            for (int i = 0; i < 32; i++) {
                const float xv = s_red[i * 128 + pp];
                acc0 = fmaf(s_w1[wb + i],       xv, acc0);
                acc1 = fmaf(s_w1[wb + 256 + i], xv, acc1);
                acc2 = fmaf(s_w1[wb + 512 + i], xv, acc2);
                acc3 = fmaf(s_w1[wb + 768 + i], xv, acc3);
            }
            s_y[t7 * 128 + pp]        = acc0;
            s_y[(8 + t7) * 128 + pp]  = acc1;
            s_y[(16 + t7) * 128 + pp] = acc2;
            s_y[(24 + t7) * 128 + pp] = acc3;
        }
        __syncthreads();                      // B2

        // ---- GroupNorm(128) + h-swish, warp per channel ----
        {
            float* yr = s_y + c * 128;
            float v0 = yr[lane], v1 = yr[lane + 32], v2 = yr[lane + 64], v3 = yr[lane + 96];
            float s1 = (v0 + v1) + (v2 + v3);
            float s2 = fmaf(v0, v0, fmaf(v1, v1, fmaf(v2, v2, v3 * v3)));
            #pragma unroll
            for (int o = 16; o; o >>= 1) {
                s1 += __shfl_xor_sync(0xffffffffu, s1, o);
                s2 += __shfl_xor_sync(0xffffffffu, s2, o);
            }
            const float mu  = s1 * (1.f / 128.f);
            const float var = s2 * (1.f / 128.f) - mu * mu;
            const float gm  = s_gg[c] * rsqrtf(var + 1e-5f);
            const float gc  = fmaf(-mu, gm, s_gb[c]);
            yr[lane]      = hswishf_(fmaf(v0, gm, gc));
            yr[lane + 32] = hswishf_(fmaf(v1, gm, gc));
            yr[lane + 64] = hswishf_(fmaf(v2, gm, gc));
            yr[lane + 96] = hswishf_(fmaf(v3, gm, gc));
        }
        __syncthreads();                      // B3

        // ---- conv_h/conv_w, register-blocked -> s_a (alias s_red) ----
        {
            const float* w  = (pp < 64) ? s_wh : s_ww;
            const float* bs = (pp < 64) ? s_bh : s_bw;
            float acc0 = bs[t7], acc1 = bs[8 + t7], acc2 = bs[16 + t7], acc3 = bs[24 + t7];
            const int wb = t7 * 32;
            #pragma unroll 8
            for (int i = 0; i < 32; i++) {
                const float yv = s_y[i * 128 + pp];
                acc0 = fmaf(w[wb + i],       yv, acc0);
                acc1 = fmaf(w[wb + 256 + i], yv, acc1);
                acc2 = fmaf(w[wb + 512 + i], yv, acc2);
                acc3 = fmaf(w[wb + 768 + i], yv, acc3);
            }
            s_a[t7 * 128 + pp]        = acc0;
            s_a[(8 + t7) * 128 + pp]  = acc1;
            s_a[(16 + t7) * 128 + pp] = acc2;
            s_a[(24 + t7) * 128 + pp] = acc3;
        }
        __syncthreads();                      // B4: publishes s_a

        // ---- Pass B: gate + channel-shuffled store (L2-hit re-read) ----
        const float xsv = s_xs[c];
        float4 aw = ((const float4*)(s_a + c * 128 + 64))[q];
        const float g0 = aw.x * xsv, g1 = aw.y * xsv, g2 = aw.z * xsv, g3 = aw.w * xsv;
        float4* od = (float4*)(out + ((size_t)(n * 512 + shuffle_out_ch(g * 64 + 32 + c))) * 4096);
        #pragma unroll
        for (int tt = 0; tt < 32; tt += 8) {
            float4 v[8];
            #pragma unroll
            for (int j = 0; j < 8; j++) v[j] = __ldcs(&xc4[(tt + j) * 32 + lane]);
            #pragma unroll
            for (int j = 0; j < 8; j++) {
                const float ah = s_a[c * 128 + 2 * (tt + j) + half];
                v[j].x *= sigapx_(ah * g0);
                v[j].y *= sigapx_(ah * g1);
                v[j].z *= sigapx_(ah * g2);
                v[j].w *= sigapx_(ah * g3);
                __stcs(&od[(tt + j) * 32 + lane], v[j]);
            }
        }
    }

    // ---- self-reset for the next graph replay (last CTA zeroes counters) ----
    if (tid == 0) {
        __threadfence();                       // order final g_counter add before g_done add
        const unsigned d = atomicAdd(&g_done, 1u);
        if (d == NCTAS - 1) {
            g_counter = 0u;
            g_done    = 0u;
        }
    }
}

extern "C" void kernel_launch(void* const* d_in, const int* in_sizes, int n_in,
                              void* d_out, int out_size) {
    const float* x       = (const float*)d_in[0];
    const float* cweight = (const float*)d_in[1];
    const float* cbias   = (const float*)d_in[2];
    const float* conv1_w = (const float*)d_in[3];
    const float* conv1_b = (const float*)d_in[4];
    const float* gn_g    = (const float*)d_in[5];
    const float* gn_b    = (const float*)d_in[6];
    const float* convh_w = (const float*)d_in[7];
    const float* convh_b = (const float*)d_in[8];
    const float* convw_w = (const float*)d_in[9];
    const float* convw_b = (const float*)d_in[10];
    float* out = (float*)d_out;

    scsa_persistent<<<NCTAS, THREADS>>>(
        x, cweight, cbias, conv1_w, conv1_b, gn_g, gn_b,
        convh_w, convh_b, convw_w, convw_b, out);
}

// round 15
// speedup vs baseline: 1.1055x; 1.1055x over previous
#include <cuda_runtime.h>

// SCSA fused v13 = v8 VERBATIM (152x1024 persistent occ-1, loop-top steal
// between two barriers, v8's LPT schedule: ids 0..511 = spatial/quarter
// alternating, ids 512..1279 = pure quarters so the tail is fine-grained,
// position-blocked convs, .cs streaming, unroll-8) + self-resetting counters
// (last CTA zeroes g_counter/g_done) so the reset launch is gone and the
// graph is a single node. Nothing else changed vs v8.

#define NCTAS   152
#define THREADS 1024
#define NUNITS  1280

__device__ unsigned int g_counter = 0u;
__device__ unsigned int g_done    = 0u;

__device__ __forceinline__ float sigmoidf_(float z) {
    return 1.f / (1.f + __expf(-z));
}
__device__ __forceinline__ float sigapx_(float z) {
    float t;
    asm("tanh.approx.f32 %0, %1;" : "=f"(t) : "f"(z * 0.5f));
    return fmaf(0.5f, t, 0.5f);
}
__device__ __forceinline__ float hswishf_(float z) {
    return z * __saturatef((z + 3.f) * (1.f / 6.f));
}
__device__ __forceinline__ int shuffle_out_ch(int p) {
    return (p < 256) ? (2 * p) : (2 * (p - 256) + 1);
}

__global__ __launch_bounds__(THREADS, 1) void scsa_persistent(
    const float* __restrict__ x,
    const float* __restrict__ cweight, const float* __restrict__ cbias,
    const float* __restrict__ conv1_w, const float* __restrict__ conv1_b,
    const float* __restrict__ gn_g,    const float* __restrict__ gn_b,
    const float* __restrict__ convh_w, const float* __restrict__ convh_b,
    const float* __restrict__ convw_w, const float* __restrict__ convw_b,
    float* __restrict__ out)
{
    __shared__ float s_red[4096];   // row c: xh[0..63] | xw[64..127]; aliased a_h|a_w
    __shared__ float s_y[4096];
    __shared__ float s_w1[1024], s_wh[1024], s_ww[1024];
    __shared__ float s_b1[32], s_bh[32], s_bw[32], s_gg[32], s_gb[32], s_xs[32];
    __shared__ float s_part[32];    // channel-quarter partials [ch8*4 + rowblk]
    __shared__ float s_gate[8];
    __shared__ unsigned s_u;
    float* s_a = s_red;

    const int tid  = threadIdx.x;
    const int wid  = tid >> 5;       // warp id; spatial: warp = channel c
    const int lane = tid & 31;
    const int half = lane >> 4;
    const int q    = lane & 15;
    const int t7   = tid >> 7;       // 0..7 conv output-block id
    const int pp   = tid & 127;      // conv position id
    const int c    = wid;

    // stage weights once
    s_w1[tid] = conv1_w[tid];
    s_wh[tid] = convh_w[tid];
    s_ww[tid] = convw_w[tid];
    if (tid < 32) {
        s_b1[tid] = conv1_b[tid]; s_bh[tid] = convh_b[tid]; s_bw[tid] = convw_b[tid];
        s_gg[tid] = gn_g[tid];    s_gb[tid] = gn_b[tid];
    }

    while (true) {
        __syncthreads();                 // smem quiesce + weight publish
        if (tid == 0) s_u = atomicAdd(&g_counter, 1u);
        __syncthreads();
        const unsigned u = s_u;
        if (u >= NUNITS) break;

        // ---------------- unit decode (v8 LPT schedule) ----------------
        const bool is_spatial = (u < 512) && !(u & 1u);
        int bb, qd = 0;
        if (is_spatial) {
            bb = (int)(u >> 1);
        } else {
            const int cq = (u < 512) ? (int)(u >> 1) : (int)(u - 256);
            bb = cq >> 2; qd = cq & 3;
        }
        const int n = bb >> 3, g = bb & 7;

        if (!is_spatial) {
            // ========== channel-quarter: x0 channels g*64 + qd*8 + [0,8) ==========
            const int ch8 = wid & 7;
            const int rb  = wid >> 3;
            const int cglob = g * 64 + qd * 8 + ch8;
            const float4* xq4 = (const float4*)(x + ((size_t)(n * 512 + cglob)) * 4096)
                              + rb * 256;
            float s = 0.f;
            {
                float4 v[8];
                #pragma unroll
                for (int j = 0; j < 8; j++) v[j] = xq4[j * 32 + lane];
                #pragma unroll
                for (int j = 0; j < 8; j++)
                    s += (v[j].x + v[j].y) + (v[j].z + v[j].w);
            }
            #pragma unroll
            for (int o = 16; o; o >>= 1) s += __shfl_xor_sync(0xffffffffu, s, o);
            if (lane == 0) s_part[ch8 * 4 + rb] = s;
            __syncthreads();                  // B1: publishes s_part
            if (tid < 8) {
                const float tot = s_part[tid * 4] + s_part[tid * 4 + 1]
                                + s_part[tid * 4 + 2] + s_part[tid * 4 + 3];
                const int cg = qd * 8 + tid;
                s_gate[tid] = sigmoidf_(cweight[cg] * (tot * (1.f / 4096.f)) + cbias[cg]);
            }
            __syncthreads();                  // B2: publishes s_gate
            const float gate = s_gate[ch8];
            float4* od = (float4*)(out + ((size_t)(n * 512 + shuffle_out_ch(cglob))) * 4096)
                       + rb * 256;
            {
                float4 v[8];
                #pragma unroll
                for (int j = 0; j < 8; j++) v[j] = __ldcs(&xq4[j * 32 + lane]);
                #pragma unroll
                for (int j = 0; j < 8; j++) {
                    v[j].x *= gate; v[j].y *= gate; v[j].z *= gate; v[j].w *= gate;
                    __stcs(&od[j * 32 + lane], v[j]);
                }
            }
            continue;
        }

        // ================= spatial unit: x1 of block bb =================
        const float4* xc4 = (const float4*)(x + ((size_t)(n * 512 + g * 64 + 32 + c)) * 4096);

        // ---- Pass A: row/col/total means. 8 loads in flight per warp. ----
        float cs0 = 0.f, cs1 = 0.f, cs2 = 0.f, cs3 = 0.f, xs = 0.f;
        #pragma unroll
        for (int tt = 0; tt < 32; tt += 8) {
            float4 v[8];
            #pragma unroll
            for (int j = 0; j < 8; j++) v[j] = xc4[(tt + j) * 32 + lane];
            float r8[8];
            #pragma unroll
            for (int j = 0; j < 8; j++) {
                cs0 += v[j].x; cs1 += v[j].y; cs2 += v[j].z; cs3 += v[j].w;
                r8[j] = (v[j].x + v[j].y) + (v[j].z + v[j].w);
                xs += r8[j];
            }
            #pragma unroll
            for (int o = 8; o; o >>= 1) {
                #pragma unroll
                for (int j = 0; j < 8; j++)
                    r8[j] += __shfl_xor_sync(0xffffffffu, r8[j], o);
            }
            if (q == 0) {
                #pragma unroll
                for (int j = 0; j < 8; j++)
                    s_red[c * 128 + 2 * (tt + j) + half] = r8[j] * (1.f / 64.f);
            }
        }
        cs0 += __shfl_xor_sync(0xffffffffu, cs0, 16);
        cs1 += __shfl_xor_sync(0xffffffffu, cs1, 16);
        cs2 += __shfl_xor_sync(0xffffffffu, cs2, 16);
        cs3 += __shfl_xor_sync(0xffffffffu, cs3, 16);
        #pragma unroll
        for (int o = 16; o; o >>= 1) xs += __shfl_xor_sync(0xffffffffu, xs, o);
        if (half == 0) {
            ((float4*)(s_red + c * 128 + 64))[q] = make_float4(
                cs0 * (1.f / 64.f), cs1 * (1.f / 64.f),
                cs2 * (1.f / 64.f), cs3 * (1.f / 64.f));
        }
        if (lane == 0) s_xs[c] = xs * (1.f / 4096.f);
        __syncthreads();                      // B1: publishes s_red, s_xs

        // ---- conv1, register-blocked: outputs o = t7, 8+t7, 16+t7, 24+t7 ----
        {
            float acc0 = s_b1[t7], acc1 = s_b1[8 + t7], acc2 = s_b1[16 + t7], acc3 = s_b1[24 + t7];
            const int wb = t7 * 32;
            #pragma unroll 8
            for (int i = 0; i < 32; i++) {
                const float xv = s_red[i * 128 + pp];
                acc0 = fmaf(s_w1[wb + i],       xv, acc0);
                acc1 = fmaf(s_w1[wb + 256 + i], xv, acc1);
                acc2 = fmaf(s_w1[wb + 512 + i], xv, acc2);
                acc3 = fmaf(s_w1[wb + 768 + i], xv, acc3);
            }
            s_y[t7 * 128 + pp]        = acc0;
            s_y[(8 + t7) * 128 + pp]  = acc1;
            s_y[(16 + t7) * 128 + pp] = acc2;
            s_y[(24 + t7) * 128 + pp] = acc3;
        }
        __syncthreads();                      // B2

        // ---- GroupNorm(128) + h-swish, warp per channel ----
        {
            float* yr = s_y + c * 128;
            float v0 = yr[lane], v1 = yr[lane + 32], v2 = yr[lane + 64], v3 = yr[lane + 96];
            float s1 = (v0 + v1) + (v2 + v3);
            float s2 = fmaf(v0, v0, fmaf(v1, v1, fmaf(v2, v2, v3 * v3)));
            #pragma unroll
            for (int o = 16; o; o >>= 1) {
                s1 += __shfl_xor_sync(0xffffffffu, s1, o);
                s2 += __shfl_xor_sync(0xffffffffu, s2, o);
            }
            const float mu  = s1 * (1.f / 128.f);
            const float var = s2 * (1.f / 128.f) - mu * mu;
            const float gm  = s_gg[c] * rsqrtf(var + 1e-5f);
            const float gc  = fmaf(-mu, gm, s_gb[c]);
            yr[lane]      = hswishf_(fmaf(v0, gm, gc));
            yr[lane + 32] = hswishf_(fmaf(v1, gm, gc));
            yr[lane + 64] = hswishf_(fmaf(v2, gm, gc));
            yr[lane + 96] = hswishf_(fmaf(v3, gm, gc));
        }
        __syncthreads();                      // B3

        // ---- conv_h/conv_w, register-blocked -> s_a (alias s_red) ----
        {
            const float* w  = (pp < 64) ? s_wh : s_ww;
            const float* bs = (pp < 64) ? s_bh : s_bw;
            float acc0 = bs[t7], acc1 = bs[8 + t7], acc2 = bs[16 + t7], acc3 = bs[24 + t7];
            const int wb = t7 * 32;
            #pragma unroll 8
            for (int i = 0; i < 32; i++) {
                const float yv = s_y[i * 128 + pp];
                acc0 = fmaf(w[wb + i],       yv, acc0);
                acc1 = fmaf(w[wb + 256 + i], yv, acc1);
                acc2 = fmaf(w[wb + 512 + i], yv, acc2);
                acc3 = fmaf(w[wb + 768 + i], yv, acc3);
            }
            s_a[t7 * 128 + pp]        = acc0;
            s_a[(8 + t7) * 128 + pp]  = acc1;
            s_a[(16 + t7) * 128 + pp] = acc2;
            s_a[(24 + t7) * 128 + pp] = acc3;
        }
        __syncthreads();                      // B4: publishes s_a

        // ---- Pass B: gate + channel-shuffled store (L2-hit re-read) ----
        const float xsv = s_xs[c];
        float4 aw = ((const float4*)(s_a + c * 128 + 64))[q];
        const float g0 = aw.x * xsv, g1 = aw.y * xsv, g2 = aw.z * xsv, g3 = aw.w * xsv;
        float4* od = (float4*)(out + ((size_t)(n * 512 + shuffle_out_ch(g * 64 + 32 + c))) * 4096);
        #pragma unroll
        for (int tt = 0; tt < 32; tt += 8) {
            float4 v[8];
            #pragma unroll
            for (int j = 0; j < 8; j++) v[j] = __ldcs(&xc4[(tt + j) * 32 + lane]);
            #pragma unroll
            for (int j = 0; j < 8; j++) {
                const float ah = s_a[c * 128 + 2 * (tt + j) + half];
                v[j].x *= sigapx_(ah * g0);
                v[j].y *= sigapx_(ah * g1);
                v[j].z *= sigapx_(ah * g2);
                v[j].w *= sigapx_(ah * g3);
                __stcs(&od[(tt + j) * 32 + lane], v[j]);
            }
        }
    }

    // ---- self-reset for the next graph replay (last CTA zeroes counters) ----
    if (tid == 0) {
        __threadfence();                       // order final g_counter add before g_done add
        const unsigned d = atomicAdd(&g_done, 1u);
        if (d == NCTAS - 1) {
            g_counter = 0u;
            g_done    = 0u;
        }
    }
}

extern "C" void kernel_launch(void* const* d_in, const int* in_sizes, int n_in,
                              void* d_out, int out_size) {
    const float* x       = (const float*)d_in[0];
    const float* cweight = (const float*)d_in[1];
    const float* cbias   = (const float*)d_in[2];
    const float* conv1_w = (const float*)d_in[3];
    const float* conv1_b = (const float*)d_in[4];
    const float* gn_g    = (const float*)d_in[5];
    const float* gn_b    = (const float*)d_in[6];
    const float* convh_w = (const float*)d_in[7];
    const float* convh_b = (const float*)d_in[8];
    const float* convw_w = (const float*)d_in[9];
    const float* convw_b = (const float*)d_in[10];
    float* out = (float*)d_out;

    scsa_persistent<<<NCTAS, THREADS>>>(
        x, cweight, cbias, conv1_w, conv1_b, gn_g, gn_b,
        convh_w, convh_b, convw_w, convw_b, out);
}